// round 16
// baseline (speedup 1.0000x reference)
#include <cuda_runtime.h>
#include <cuda_bf16.h>
#include <math.h>
#include <stdint.h>

#define NT 9
#define NN 50000
#define NE 800000
#define NREL 15
#define DIN 64
#define HH 128

__device__ __constant__ int   c_src[NREL]   = {0,1,0,2,1,0,3,3,0,4,0,1,0,0,5};
__device__ __constant__ int   c_dst[NREL]   = {1,0,2,0,2,3,0,7,4,0,8,4,6,5,0};
__device__ __constant__ float c_invcnt[NT]  = {1.f/5.f,1.f,1.f/2.f,1.f,1.f/2.f,1.f,1.f,1.f,1.f};
__device__ __constant__ int   c_nseg[NT]    = {6,2,3,2,3,2,2,2,2};
__device__ __constant__ int   c_segrel[NT][6] = {
    {-1,1,3,6,9,14},{-1,0,0,0,0,0},{-1,2,4,0,0,0},{-1,5,0,0,0,0},
    {-1,8,11,0,0,0},{-1,13,0,0,0,0},{-1,12,0,0,0,0},{-1,7,0,0,0,0},{-1,10,0,0,0,0}};

// Scratch (device globals: allocation-free rule)
__device__ float g_xs0[(size_t)NT*NN*HH];
__device__ float g_xs1[(size_t)NT*NN*HH];
__device__ __nv_bfloat16 g_xbf[(size_t)NT*NN*HH];
__device__ float g_msgs[(size_t)NREL*NN*HH];
__device__ float g_part[NT*NN];
__device__ int   g_cnt[NREL*NN];
__device__ int   g_off[NREL*(NN+1)];
__device__ int   g_tmp[NREL*NN];
__device__ int   g_csrc[(size_t)NREL*NE];
__device__ float g_wrc[3ull*NT*HH*HH];
__device__ float g_bc[3*NT*HH];

__device__ __forceinline__ void cp16(uint32_t dst, const void* src) {
    asm volatile("cp.async.cg.shared.global [%0], [%1], 16;" :: "r"(dst), "l"(src));
}

// ---------------------------------------------------------------------------
// hist (g_cnt pre-zeroed by cudaMemsetAsync) + bf16 shadow convert, 4x vector
// ---------------------------------------------------------------------------
__global__ void k_hist_cvt(const int* __restrict__ edges, const float* __restrict__ x) {
    int i = blockIdx.x * blockDim.x + threadIdx.x;
    if (i < NREL * NE / 4) {
        int r = i / (NE / 4);
        int e4 = i - r * (NE / 4);
        int4 d = reinterpret_cast<const int4*>(edges + (size_t)r * 2 * NE + NE)[e4];
        int* cnt = g_cnt + r * NN;
        atomicAdd(&cnt[d.x], 1);
        atomicAdd(&cnt[d.y], 1);
        atomicAdd(&cnt[d.z], 1);
        atomicAdd(&cnt[d.w], 1);
    }
    if (i < NT * NN * DIN / 4) {
        float4 v = reinterpret_cast<const float4*>(x)[i];
        __nv_bfloat162 lo = __floats2bfloat162_rn(v.x, v.y);
        __nv_bfloat162 hi = __floats2bfloat162_rn(v.z, v.w);
        uint2 u;
        u.x = *reinterpret_cast<uint32_t*>(&lo);
        u.y = *reinterpret_cast<uint32_t*>(&hi);
        reinterpret_cast<uint2*>(g_xbf)[i] = u;
    }
}

__global__ void k_scan() {
    int r = blockIdx.x;
    int t = threadIdx.x;
    __shared__ int s[1024];
    int carry = 0;
    for (int base = 0; base < NN; base += 1024) {
        int i = base + t;
        int v = (i < NN) ? g_cnt[r * NN + i] : 0;
        s[t] = v;
        __syncthreads();
        #pragma unroll
        for (int d = 1; d < 1024; d <<= 1) {
            int x = (t >= d) ? s[t - d] : 0;
            __syncthreads();
            s[t] += x;
            __syncthreads();
        }
        int excl = carry + s[t] - v;
        if (i < NN) {
            g_off[r * (NN + 1) + i] = excl;
            g_tmp[r * NN + i] = excl;
        }
        carry += s[1023];
        __syncthreads();
    }
    if (t == 0) g_off[r * (NN + 1) + NN] = carry;
}

__global__ void k_fill(const int* __restrict__ edges) {
    int i = blockIdx.x * blockDim.x + threadIdx.x;
    if (i >= NREL * NE / 4) return;
    int r = i / (NE / 4);
    int e4 = i - r * (NE / 4);
    const int* base = edges + (size_t)r * 2 * NE;
    int4 s = reinterpret_cast<const int4*>(base)[e4];
    int4 d = reinterpret_cast<const int4*>(base + NE)[e4];
    int* tmp = g_tmp + r * NN;
    int* csr = g_csrc + (size_t)r * NE;
    csr[atomicAdd(&tmp[d.x], 1)] = s.x;
    csr[atomicAdd(&tmp[d.y], 1)] = s.y;
    csr[atomicAdd(&tmp[d.z], 1)] = s.z;
    csr[atomicAdd(&tmp[d.w], 1)] = s.w;
}

// ---------------------------------------------------------------------------
// Combine Wr / b across relations sharing a dst type (per-layer banks)
// ---------------------------------------------------------------------------
template <int K>
__global__ void k_combW(const float* __restrict__ Wr, float* __restrict__ wrc) {
    int idx = blockIdx.x * blockDim.x + threadIdx.x;
    if (idx >= NT * K * HH) return;
    int i = idx / (K * HH);
    int j = idx - i * (K * HH);
    float s = 0.f;
    #pragma unroll
    for (int r = 0; r < NREL; r++)
        if (c_dst[r] == i) s += Wr[(size_t)r * K * HH + j];
    wrc[(size_t)i * K * HH + j] = s;
}

__global__ void k_combB3(const float* __restrict__ b1, const float* __restrict__ b2,
                         const float* __restrict__ b3, float* __restrict__ bc) {
    int idx = blockIdx.x * blockDim.x + threadIdx.x;
    if (idx >= 3 * NT * HH) return;
    int layer = idx / (NT * HH);
    int rem = idx - layer * (NT * HH);
    int i = rem / HH;
    int j = rem - i * HH;
    const float* b = (layer == 0) ? b1 : (layer == 1) ? b2 : b3;
    float s = 0.f;
    #pragma unroll
    for (int r = 0; r < NREL; r++)
        if (c_dst[r] == i) s += b[r * HH + j];
    bc[idx] = s;
}

// ---------------------------------------------------------------------------
// bf16 gather aggregation with cp.async smem ring (register-free MLP).
// Warp = 1 dst row; D=128: half-warp per edge (2 edges/group);
// D=64: quarter-warp per edge (4 edges/group). NSLOT=4 groups in flight.
// Accumulation order identical to the direct-LDG version (bitwise same result).
// ---------------------------------------------------------------------------
__device__ __forceinline__ void accu4(float* a, uint4 u) {
    a[0] += __uint_as_float(u.x << 16);
    a[1] += __uint_as_float(u.x & 0xFFFF0000u);
    a[2] += __uint_as_float(u.y << 16);
    a[3] += __uint_as_float(u.y & 0xFFFF0000u);
    a[4] += __uint_as_float(u.z << 16);
    a[5] += __uint_as_float(u.z & 0xFFFF0000u);
    a[6] += __uint_as_float(u.w << 16);
    a[7] += __uint_as_float(u.w & 0xFFFF0000u);
}

#define NSLOT 4

template <int D>
__global__ void k_agg() {
    constexpr int EPG   = (D == 128) ? 2 : 4;   // edges per group
    constexpr int TPR   = 32 / EPG;             // threads per edge row-slice
    constexpr int SHIFT = (D == 128) ? 8 : 7;   // log2(row bytes)
    __shared__ uint4 ring[8][NSLOT][32];

    int r = blockIdx.y;
    int wid = threadIdx.x >> 5;
    int lane = threadIdx.x & 31;
    int row = blockIdx.x * 8 + wid;
    const char* __restrict__ bp =
        reinterpret_cast<const char*>(g_xbf + (size_t)c_src[r] * NN * D);
    float* __restrict__ msg = g_msgs + (size_t)r * NN * D;
    int o0 = g_off[r * (NN + 1) + row];
    int deg = g_off[r * (NN + 1) + row + 1] - o0;
    const int* __restrict__ srcs = g_csrc + (size_t)r * NE + o0;
    float inv = (deg > 0) ? 1.f / (float)deg : 0.f;

    int seg = lane / TPR;                       // edge index within group
    unsigned subo = (unsigned)(lane % TPR) << 4;
    uint32_t slot0 = (uint32_t)__cvta_generic_to_shared(&ring[wid][0][lane]);
    int ng = (deg + EPG - 1) / EPG;

    auto issue = [&](int g) {
        if (g < ng) {                           // warp-uniform predicate
            int e = g * EPG + seg;
            if (e > deg - 1) e = deg - 1;
            unsigned s = (unsigned)srcs[e];
            cp16(slot0 + (uint32_t)(g & (NSLOT - 1)) * 512,
                 bp + (((size_t)s << SHIFT) + subo));
        }
        asm volatile("cp.async.commit_group;" ::: "memory");
    };

    float a[8] = {0.f, 0.f, 0.f, 0.f, 0.f, 0.f, 0.f, 0.f};

    #pragma unroll
    for (int g = 0; g < NSLOT; g++) issue(g);
    for (int g = 0; g < ng; g++) {
        asm volatile("cp.async.wait_group %0;" :: "n"(NSLOT - 1) : "memory");
        uint4 u = ring[wid][g & (NSLOT - 1)][lane];
        if (g * EPG + seg < deg) accu4(a, u);
        issue(g + NSLOT);
    }
    asm volatile("cp.async.wait_group 0;" ::: "memory");

    if (D == 128) {
        #pragma unroll
        for (int k = 0; k < 8; k++)
            a[k] += __shfl_down_sync(0xffffffffu, a[k], 16);
        if (lane < 16) {
            float* mp = msg + (size_t)row * 128 + lane * 8;
            float4 v0 = make_float4(a[0] * inv, a[1] * inv, a[2] * inv, a[3] * inv);
            float4 v1 = make_float4(a[4] * inv, a[5] * inv, a[6] * inv, a[7] * inv);
            reinterpret_cast<float4*>(mp)[0] = v0;
            reinterpret_cast<float4*>(mp)[1] = v1;
        }
    } else {
        #pragma unroll
        for (int k = 0; k < 8; k++) {
            a[k] += __shfl_down_sync(0xffffffffu, a[k], 16);
            a[k] += __shfl_down_sync(0xffffffffu, a[k], 8);
        }
        if (lane < 8) {
            float* mp = msg + (size_t)row * 64 + lane * 8;
            float4 v0 = make_float4(a[0] * inv, a[1] * inv, a[2] * inv, a[3] * inv);
            float4 v1 = make_float4(a[4] * inv, a[5] * inv, a[6] * inv, a[7] * inv);
            reinterpret_cast<float4*>(mp)[0] = v0;
            reinterpret_cast<float4*>(mp)[1] = v1;
        }
    }
}

// ---------------------------------------------------------------------------
// TF32 mma. A fragments re-rounded with cvt.rna in registers; B raw-truncated.
// ---------------------------------------------------------------------------
__device__ __forceinline__ uint32_t f2tf32(float f) {
    uint32_t u;
    asm("cvt.rna.tf32.f32 %0, %1;" : "=r"(u) : "f"(f));
    return u;
}

__device__ __forceinline__ void mma_tf32(float* d, const uint32_t* a, const uint32_t* b) {
    asm volatile(
        "mma.sync.aligned.m16n8k8.row.col.f32.tf32.tf32.f32 "
        "{%0,%1,%2,%3}, {%4,%5,%6,%7}, {%8,%9}, {%0,%1,%2,%3};"
        : "+f"(d[0]), "+f"(d[1]), "+f"(d[2]), "+f"(d[3])
        : "r"(a[0]), "r"(a[1]), "r"(a[2]), "r"(a[3]), "r"(b[0]), "r"(b[1]));
}

#define APAD 36
#define BPAD 136
#define ATILE (128 * APAD)
#define BTILE (32 * BPAD)
#define GSMEM ((2 * ATILE + 2 * BTILE) * 4)

// ---------------------------------------------------------------------------
// Segmented TF32 GEMM + fused leaky-ReLU + LayerNorm, cp.async double-buffered.
// BM=128, BK=32, 8 warps. FINAL layer fuses the FC dot product into g_part.
// ---------------------------------------------------------------------------
template <int SK, bool WRITEBF, bool FINAL>
__global__ void __launch_bounds__(256) k_gemm_ln(const float* __restrict__ xin,
                                                const float* __restrict__ Wl,
                                                const float* __restrict__ wrc,
                                                const float* __restrict__ bc,
                                                const float* __restrict__ gam,
                                                const float* __restrict__ bet,
                                                float* __restrict__ out,
                                                const float* __restrict__ Wfc) {
    extern __shared__ uint32_t smem[];
    uint32_t* sA = smem;                  // 2 x ATILE
    uint32_t* sB = smem + 2 * ATILE;      // 2 x BTILE

    int tid = threadIdx.x;
    int lane = tid & 31;
    int w = tid >> 5;
    int type = blockIdx.y;
    int r0 = blockIdx.x * 128;

    uint32_t sAu = (uint32_t)__cvta_generic_to_shared(sA);
    uint32_t sBu = (uint32_t)__cvta_generic_to_shared(sB);

    constexpr int CH = SK / 32;
    int nchunk = c_nseg[type] * CH;

    auto issue = [&](int c, int buf) {
        int seg = c / CH;
        int off = (c - seg * CH) * 32;
        int rel = c_segrel[type][seg];
        const float* Ab = (seg == 0) ? xin + (size_t)type * NN * SK
                                     : g_msgs + (size_t)rel * NN * SK;
        const float* Bb = (seg == 0) ? wrc + (size_t)type * SK * HH
                                     : Wl + (size_t)rel * SK * HH;
        uint32_t dA = sAu + (uint32_t)buf * ATILE * 4;
        uint32_t dB = sBu + (uint32_t)buf * BTILE * 4;
        #pragma unroll
        for (int l = 0; l < 4; l++) {
            int f = tid + l * 256;
            int row = f >> 3;
            int c0 = (f & 7) * 4;
            int grow = r0 + row;
            if (grow > NN - 1) grow = NN - 1;   // clamp: junk rows masked at epilogue
            cp16(dA + (uint32_t)(row * APAD + c0) * 4,
                 Ab + (size_t)grow * SK + off + c0);
        }
        #pragma unroll
        for (int l = 0; l < 4; l++) {
            int f = tid + l * 256;
            int krow = f >> 5;
            int n0 = (f & 31) * 4;
            cp16(dB + (uint32_t)(krow * BPAD + n0) * 4,
                 Bb + (size_t)(off + krow) * HH + n0);
        }
        asm volatile("cp.async.commit_group;");
    };

    float acc[16][4];
    #pragma unroll
    for (int nt = 0; nt < 16; nt++)
        #pragma unroll
        for (int j = 0; j < 4; j++) acc[nt][j] = 0.f;

    issue(0, 0);
    for (int c = 0; c < nchunk; c++) {
        int buf = c & 1;
        if (c + 1 < nchunk) {
            issue(c + 1, buf ^ 1);
            asm volatile("cp.async.wait_group 1;");
        } else {
            asm volatile("cp.async.wait_group 0;");
        }
        __syncthreads();
        const uint32_t* cA = sA + buf * ATILE;
        const uint32_t* cB = sB + buf * BTILE;
        #pragma unroll
        for (int kt = 0; kt < 4; kt++) {
            int abase = (w * 16 + (lane >> 2)) * APAD + kt * 8 + (lane & 3);
            uint32_t af[4];
            af[0] = f2tf32(__uint_as_float(cA[abase]));
            af[1] = f2tf32(__uint_as_float(cA[abase + 8 * APAD]));
            af[2] = f2tf32(__uint_as_float(cA[abase + 4]));
            af[3] = f2tf32(__uint_as_float(cA[abase + 8 * APAD + 4]));
            int bb = (kt * 8 + (lane & 3)) * BPAD + (lane >> 2);
            #pragma unroll
            for (int nt = 0; nt < 16; nt++) {
                uint32_t bf[2];
                bf[0] = cB[bb + nt * 8];
                bf[1] = cB[bb + nt * 8 + 4 * BPAD];
                mma_tf32(acc[nt], af, bf);
            }
        }
        __syncthreads();
    }

    // ---- fused epilogue ----
    float inv = c_invcnt[type];
    #pragma unroll
    for (int h = 0; h < 2; h++) {
        int row = r0 + w * 16 + (lane >> 2) + h * 8;
        float v[16][2];
        float s = 0.f;
        #pragma unroll
        for (int nt = 0; nt < 16; nt++) {
            int col = nt * 8 + (lane & 3) * 2;
            float x0 = (acc[nt][2 * h] + bc[type * HH + col]) * inv;
            float x1 = (acc[nt][2 * h + 1] + bc[type * HH + col + 1]) * inv;
            x0 = (x0 >= 0.f) ? x0 : 0.01f * x0;
            x1 = (x1 >= 0.f) ? x1 : 0.01f * x1;
            v[nt][0] = x0; v[nt][1] = x1;
            s += x0 + x1;
        }
        s += __shfl_xor_sync(0xffffffffu, s, 1);
        s += __shfl_xor_sync(0xffffffffu, s, 2);
        float mu = s * (1.f / HH);
        float q = 0.f;
        #pragma unroll
        for (int nt = 0; nt < 16; nt++) {
            float d0 = v[nt][0] - mu, d1 = v[nt][1] - mu;
            v[nt][0] = d0; v[nt][1] = d1;
            q += d0 * d0 + d1 * d1;
        }
        q += __shfl_xor_sync(0xffffffffu, q, 1);
        q += __shfl_xor_sync(0xffffffffu, q, 2);
        float rs = rsqrtf(q * (1.f / HH) + 1e-5f);
        if (FINAL) {
            float dot = 0.f;
            #pragma unroll
            for (int nt = 0; nt < 16; nt++) {
                int col = nt * 8 + (lane & 3) * 2;
                float o0 = v[nt][0] * rs * gam[col] + bet[col];
                float o1 = v[nt][1] * rs * gam[col + 1] + bet[col + 1];
                dot += o0 * Wfc[type * HH + col] + o1 * Wfc[type * HH + col + 1];
            }
            dot += __shfl_xor_sync(0xffffffffu, dot, 1);
            dot += __shfl_xor_sync(0xffffffffu, dot, 2);
            if ((lane & 3) == 0 && row < NN)
                g_part[type * NN + row] = dot;
        } else if (row < NN) {
            float* op = out + (size_t)type * NN * HH + (size_t)row * HH;
            __nv_bfloat16* obf = g_xbf + (size_t)type * NN * HH + (size_t)row * HH;
            #pragma unroll
            for (int nt = 0; nt < 16; nt++) {
                int col = nt * 8 + (lane & 3) * 2;
                float2 o;
                o.x = v[nt][0] * rs * gam[col] + bet[col];
                o.y = v[nt][1] * rs * gam[col + 1] + bet[col + 1];
                *reinterpret_cast<float2*>(op + col) = o;
                if (WRITEBF)
                    *reinterpret_cast<__nv_bfloat162*>(obf + col) =
                        __floats2bfloat162_rn(o.x, o.y);
            }
        }
    }
}

// ---------------------------------------------------------------------------
// Final reduce: out[n] = sigmoid(sum_type g_part + bfc)
// ---------------------------------------------------------------------------
__global__ void k_final2(const float* __restrict__ bfc, float* __restrict__ out) {
    int n = blockIdx.x * blockDim.x + threadIdx.x;
    if (n >= NN) return;
    float s = bfc[0];
    #pragma unroll
    for (int t = 0; t < NT; t++)
        s += g_part[t * NN + n];
    out[n] = 1.f / (1.f + expf(-s));
}

// ---------------------------------------------------------------------------
// Host driver (single stream, serial)
// ---------------------------------------------------------------------------
extern "C" void kernel_launch(void* const* d_in, const int* in_sizes, int n_in,
                              void* d_out, int out_size) {
    const float* x    = (const float*)d_in[0];
    const int* edges  = (const int*)d_in[1];
    const float* Wl1  = (const float*)d_in[2];
    const float* Wr1  = (const float*)d_in[3];
    const float* b1   = (const float*)d_in[4];
    const float* Wl2  = (const float*)d_in[5];
    const float* Wr2  = (const float*)d_in[6];
    const float* b2   = (const float*)d_in[7];
    const float* Wl3  = (const float*)d_in[8];
    const float* Wr3  = (const float*)d_in[9];
    const float* b3   = (const float*)d_in[10];
    const float* g1   = (const float*)d_in[11];
    const float* be1  = (const float*)d_in[12];
    const float* g2   = (const float*)d_in[13];
    const float* be2  = (const float*)d_in[14];
    const float* g3   = (const float*)d_in[15];
    const float* be3  = (const float*)d_in[16];
    const float* Wfc  = (const float*)d_in[17];
    const float* bfc  = (const float*)d_in[18];
    float* out = (float*)d_out;

    float *p_xs0, *p_xs1, *p_wrc, *p_bc;
    int* p_cnt;
    cudaGetSymbolAddress((void**)&p_xs0, g_xs0);
    cudaGetSymbolAddress((void**)&p_xs1, g_xs1);
    cudaGetSymbolAddress((void**)&p_wrc, g_wrc);
    cudaGetSymbolAddress((void**)&p_bc, g_bc);
    cudaGetSymbolAddress((void**)&p_cnt, g_cnt);

    cudaFuncSetAttribute(k_gemm_ln<DIN, true, false>,
                         cudaFuncAttributeMaxDynamicSharedMemorySize, GSMEM);
    cudaFuncSetAttribute(k_gemm_ln<HH, true, false>,
                         cudaFuncAttributeMaxDynamicSharedMemorySize, GSMEM);
    cudaFuncSetAttribute(k_gemm_ln<HH, false, true>,
                         cudaFuncAttributeMaxDynamicSharedMemorySize, GSMEM);

    size_t wstride = (size_t)NT * HH * HH;

    // CSR build chain (g_cnt zeroed via async memset — graph-capturable)
    cudaMemsetAsync(p_cnt, 0, (size_t)NREL * NN * sizeof(int));
    k_hist_cvt<<<(NT * NN * DIN / 4 + 255) / 256, 256>>>(edges, x);
    k_scan<<<NREL, 1024>>>();
    k_fill<<<(NREL * NE / 4 + 255) / 256, 256>>>(edges);

    // layer-1 aggregation (ncu-visible launch)
    k_agg<DIN><<<dim3(NN / 8, NREL), 256>>>();

    // weight prep (all layers)
    k_combW<DIN><<<(NT * DIN * HH + 255) / 256, 256>>>(Wr1, p_wrc);
    k_combW<HH><<<(NT * HH * HH + 255) / 256, 256>>>(Wr2, p_wrc + wstride);
    k_combW<HH><<<(NT * HH * HH + 255) / 256, 256>>>(Wr3, p_wrc + 2 * wstride);
    k_combB3<<<(3 * NT * HH + 255) / 256, 256>>>(b1, b2, b3, p_bc);

    dim3 gg((NN + 127) / 128, NT);
    dim3 ga(NN / 8, NREL);

    // layer 1
    k_gemm_ln<DIN, true, false><<<gg, 256, GSMEM>>>(x, Wl1, p_wrc, p_bc,
                                                    g1, be1, p_xs0, nullptr);
    // layer 2
    k_agg<HH><<<ga, 256>>>();
    k_gemm_ln<HH, true, false><<<gg, 256, GSMEM>>>(p_xs0, Wl2, p_wrc + wstride,
                                                   p_bc + NT * HH, g2, be2,
                                                   p_xs1, nullptr);
    // layer 3 (fused FC dot -> g_part; no activation write)
    k_agg<HH><<<ga, 256>>>();
    k_gemm_ln<HH, false, true><<<gg, 256, GSMEM>>>(p_xs1, Wl3, p_wrc + 2 * wstride,
                                                   p_bc + 2 * NT * HH, g3, be3,
                                                   nullptr, Wfc);

    k_final2<<<(NN + 255) / 256, 256>>>(bfc, out);
}

// round 17
// speedup vs baseline: 1.1285x; 1.1285x over previous
#include <cuda_runtime.h>
#include <cuda_bf16.h>
#include <math.h>
#include <stdint.h>

#define NT 9
#define NN 50000
#define NE 800000
#define NREL 15
#define DIN 64
#define HH 128

__device__ __constant__ int   c_src[NREL]   = {0,1,0,2,1,0,3,3,0,4,0,1,0,0,5};
__device__ __constant__ int   c_dst[NREL]   = {1,0,2,0,2,3,0,7,4,0,8,4,6,5,0};
__device__ __constant__ float c_invcnt[NT]  = {1.f/5.f,1.f,1.f/2.f,1.f,1.f/2.f,1.f,1.f,1.f,1.f};
__device__ __constant__ int   c_nseg[NT]    = {6,2,3,2,3,2,2,2,2};
__device__ __constant__ int   c_segrel[NT][6] = {
    {-1,1,3,6,9,14},{-1,0,0,0,0,0},{-1,2,4,0,0,0},{-1,5,0,0,0,0},
    {-1,8,11,0,0,0},{-1,13,0,0,0,0},{-1,12,0,0,0,0},{-1,7,0,0,0,0},{-1,10,0,0,0,0}};

// Scratch (device globals: allocation-free rule)
__device__ float g_xs0[(size_t)NT*NN*HH];
__device__ float g_xs1[(size_t)NT*NN*HH];
__device__ __nv_bfloat16 g_xbf[(size_t)NT*NN*HH];
__device__ float g_msgs[(size_t)NREL*NN*HH];
__device__ float g_part[NT*NN];
__device__ int   g_cnt[NREL*NN];
__device__ int   g_off[NREL*(NN+1)];
__device__ int   g_tmp[NREL*NN];
__device__ int   g_csrc[(size_t)NREL*NE];
__device__ float g_wrc[3ull*NT*HH*HH];
__device__ float g_bc[3*NT*HH];

__device__ __forceinline__ void cp16(uint32_t dst, const void* src) {
    asm volatile("cp.async.cg.shared.global [%0], [%1], 16;" :: "r"(dst), "l"(src));
}

// ---------------------------------------------------------------------------
// hist (g_cnt pre-zeroed by cudaMemsetAsync) + bf16 shadow convert, 4x vector
// ---------------------------------------------------------------------------
__global__ void k_hist_cvt(const int* __restrict__ edges, const float* __restrict__ x) {
    int i = blockIdx.x * blockDim.x + threadIdx.x;
    if (i < NREL * NE / 4) {
        int r = i / (NE / 4);
        int e4 = i - r * (NE / 4);
        int4 d = reinterpret_cast<const int4*>(edges + (size_t)r * 2 * NE + NE)[e4];
        int* cnt = g_cnt + r * NN;
        atomicAdd(&cnt[d.x], 1);
        atomicAdd(&cnt[d.y], 1);
        atomicAdd(&cnt[d.z], 1);
        atomicAdd(&cnt[d.w], 1);
    }
    if (i < NT * NN * DIN / 4) {
        float4 v = reinterpret_cast<const float4*>(x)[i];
        __nv_bfloat162 lo = __floats2bfloat162_rn(v.x, v.y);
        __nv_bfloat162 hi = __floats2bfloat162_rn(v.z, v.w);
        uint2 u;
        u.x = *reinterpret_cast<uint32_t*>(&lo);
        u.y = *reinterpret_cast<uint32_t*>(&hi);
        reinterpret_cast<uint2*>(g_xbf)[i] = u;
    }
}

__global__ void k_scan() {
    int r = blockIdx.x;
    int t = threadIdx.x;
    __shared__ int s[1024];
    int carry = 0;
    for (int base = 0; base < NN; base += 1024) {
        int i = base + t;
        int v = (i < NN) ? g_cnt[r * NN + i] : 0;
        s[t] = v;
        __syncthreads();
        #pragma unroll
        for (int d = 1; d < 1024; d <<= 1) {
            int x = (t >= d) ? s[t - d] : 0;
            __syncthreads();
            s[t] += x;
            __syncthreads();
        }
        int excl = carry + s[t] - v;
        if (i < NN) {
            g_off[r * (NN + 1) + i] = excl;
            g_tmp[r * NN + i] = excl;
        }
        carry += s[1023];
        __syncthreads();
    }
    if (t == 0) g_off[r * (NN + 1) + NN] = carry;
}

__global__ void k_fill(const int* __restrict__ edges) {
    int i = blockIdx.x * blockDim.x + threadIdx.x;
    if (i >= NREL * NE / 4) return;
    int r = i / (NE / 4);
    int e4 = i - r * (NE / 4);
    const int* base = edges + (size_t)r * 2 * NE;
    int4 s = reinterpret_cast<const int4*>(base)[e4];
    int4 d = reinterpret_cast<const int4*>(base + NE)[e4];
    int* tmp = g_tmp + r * NN;
    int* csr = g_csrc + (size_t)r * NE;
    csr[atomicAdd(&tmp[d.x], 1)] = s.x;
    csr[atomicAdd(&tmp[d.y], 1)] = s.y;
    csr[atomicAdd(&tmp[d.z], 1)] = s.z;
    csr[atomicAdd(&tmp[d.w], 1)] = s.w;
}

// ---------------------------------------------------------------------------
// Combined weight prep: Wr-combine for all 3 layers + biases, one launch.
// Element layout: [0, L1W) L1 Wr; [L1W, L1W+L2W) L2; [.., +L3W) L3; then biases.
// ---------------------------------------------------------------------------
#define L1W (NT * DIN * HH)
#define LHW (NT * HH * HH)
#define WTOT (L1W + 2 * LHW)
#define BTOT (3 * NT * HH)

__global__ void k_comb_all(const float* __restrict__ Wr1, const float* __restrict__ Wr2,
                           const float* __restrict__ Wr3, const float* __restrict__ b1,
                           const float* __restrict__ b2, const float* __restrict__ b3,
                           float* __restrict__ wrc, float* __restrict__ bc) {
    int idx = blockIdx.x * blockDim.x + threadIdx.x;
    if (idx < WTOT) {
        const float* Wr;
        int K, rem, obase;
        if (idx < L1W)            { Wr = Wr1; K = DIN; rem = idx;            obase = 0; }
        else if (idx < L1W + LHW) { Wr = Wr2; K = HH;  rem = idx - L1W;      obase = L1W; }
        else                      { Wr = Wr3; K = HH;  rem = idx - L1W - LHW; obase = L1W + LHW; }
        int i = rem / (K * HH);
        int j = rem - i * (K * HH);
        float s = 0.f;
        #pragma unroll
        for (int r = 0; r < NREL; r++)
            if (c_dst[r] == i) s += Wr[(size_t)r * K * HH + j];
        wrc[obase + rem] = s;
    } else if (idx < WTOT + BTOT) {
        int bi = idx - WTOT;
        int layer = bi / (NT * HH);
        int rem = bi - layer * (NT * HH);
        int i = rem / HH;
        int j = rem - i * HH;
        const float* b = (layer == 0) ? b1 : (layer == 1) ? b2 : b3;
        float s = 0.f;
        #pragma unroll
        for (int r = 0; r < NREL; r++)
            if (c_dst[r] == i) s += b[r * HH + j];
        bc[bi] = s;
    }
}

// ---------------------------------------------------------------------------
// bf16 gather aggregation (R15 direct-LDG version: 32 regs, high occ).
// ---------------------------------------------------------------------------
__device__ __forceinline__ void accu4(float* a, uint4 u) {
    a[0] += __uint_as_float(u.x << 16);
    a[1] += __uint_as_float(u.x & 0xFFFF0000u);
    a[2] += __uint_as_float(u.y << 16);
    a[3] += __uint_as_float(u.y & 0xFFFF0000u);
    a[4] += __uint_as_float(u.z << 16);
    a[5] += __uint_as_float(u.z & 0xFFFF0000u);
    a[6] += __uint_as_float(u.w << 16);
    a[7] += __uint_as_float(u.w & 0xFFFF0000u);
}

template <int D>
__global__ void k_agg() {
    int r = blockIdx.y;
    int row = blockIdx.x * 8 + (threadIdx.x >> 5);
    int lane = threadIdx.x & 31;
    const char* __restrict__ bp =
        reinterpret_cast<const char*>(g_xbf + (size_t)c_src[r] * NN * D);
    float* __restrict__ msg = g_msgs + (size_t)r * NN * D;
    int o0 = g_off[r * (NN + 1) + row];
    int o1 = g_off[r * (NN + 1) + row + 1];
    const int* __restrict__ srcs = g_csrc + (size_t)r * NE;
    float inv = (o1 > o0) ? 1.f / (float)(o1 - o0) : 0.f;

    float a[8] = {0.f, 0.f, 0.f, 0.f, 0.f, 0.f, 0.f, 0.f};

    if (D == 128) {
        int half = lane >> 4;
        unsigned subo = (unsigned)(lane & 15) << 4;
        int e = o0;
        for (; e + 6 <= o1; e += 6) {
            unsigned s0 = (unsigned)srcs[e + half];
            unsigned s1 = (unsigned)srcs[e + 2 + half];
            unsigned s2 = (unsigned)srcs[e + 4 + half];
            uint4 u0 = *reinterpret_cast<const uint4*>(bp + ((s0 << 8) + subo));
            uint4 u1 = *reinterpret_cast<const uint4*>(bp + ((s1 << 8) + subo));
            uint4 u2 = *reinterpret_cast<const uint4*>(bp + ((s2 << 8) + subo));
            accu4(a, u0); accu4(a, u1); accu4(a, u2);
        }
        for (; e + 2 <= o1; e += 2) {
            unsigned s0 = (unsigned)srcs[e + half];
            uint4 u0 = *reinterpret_cast<const uint4*>(bp + ((s0 << 8) + subo));
            accu4(a, u0);
        }
        if (e < o1 && half == 0) {
            unsigned s0 = (unsigned)srcs[e];
            uint4 u0 = *reinterpret_cast<const uint4*>(bp + ((s0 << 8) + subo));
            accu4(a, u0);
        }
        #pragma unroll
        for (int k = 0; k < 8; k++)
            a[k] += __shfl_down_sync(0xffffffffu, a[k], 16);
        if (half == 0) {
            float* mp = msg + (size_t)row * 128 + (lane & 15) * 8;
            float4 v0 = make_float4(a[0] * inv, a[1] * inv, a[2] * inv, a[3] * inv);
            float4 v1 = make_float4(a[4] * inv, a[5] * inv, a[6] * inv, a[7] * inv);
            reinterpret_cast<float4*>(mp)[0] = v0;
            reinterpret_cast<float4*>(mp)[1] = v1;
        }
    } else {
        int q = lane >> 3;
        unsigned subo = (unsigned)(lane & 7) << 4;
        int e = o0;
        for (; e + 12 <= o1; e += 12) {
            unsigned s0 = (unsigned)srcs[e + q];
            unsigned s1 = (unsigned)srcs[e + 4 + q];
            unsigned s2 = (unsigned)srcs[e + 8 + q];
            uint4 u0 = *reinterpret_cast<const uint4*>(bp + ((s0 << 7) + subo));
            uint4 u1 = *reinterpret_cast<const uint4*>(bp + ((s1 << 7) + subo));
            uint4 u2 = *reinterpret_cast<const uint4*>(bp + ((s2 << 7) + subo));
            accu4(a, u0); accu4(a, u1); accu4(a, u2);
        }
        for (; e + 4 <= o1; e += 4) {
            unsigned s0 = (unsigned)srcs[e + q];
            uint4 u0 = *reinterpret_cast<const uint4*>(bp + ((s0 << 7) + subo));
            accu4(a, u0);
        }
        int rem = o1 - e;
        if (q < rem) {
            unsigned s0 = (unsigned)srcs[e + q];
            uint4 u0 = *reinterpret_cast<const uint4*>(bp + ((s0 << 7) + subo));
            accu4(a, u0);
        }
        #pragma unroll
        for (int k = 0; k < 8; k++) {
            a[k] += __shfl_down_sync(0xffffffffu, a[k], 16);
            a[k] += __shfl_down_sync(0xffffffffu, a[k], 8);
        }
        if (lane < 8) {
            float* mp = msg + (size_t)row * 64 + lane * 8;
            float4 v0 = make_float4(a[0] * inv, a[1] * inv, a[2] * inv, a[3] * inv);
            float4 v1 = make_float4(a[4] * inv, a[5] * inv, a[6] * inv, a[7] * inv);
            reinterpret_cast<float4*>(mp)[0] = v0;
            reinterpret_cast<float4*>(mp)[1] = v1;
        }
    }
}

// ---------------------------------------------------------------------------
// TF32 mma. A fragments re-rounded with cvt.rna in registers; B raw-truncated.
// ---------------------------------------------------------------------------
__device__ __forceinline__ uint32_t f2tf32(float f) {
    uint32_t u;
    asm("cvt.rna.tf32.f32 %0, %1;" : "=r"(u) : "f"(f));
    return u;
}

__device__ __forceinline__ void mma_tf32(float* d, const uint32_t* a, const uint32_t* b) {
    asm volatile(
        "mma.sync.aligned.m16n8k8.row.col.f32.tf32.tf32.f32 "
        "{%0,%1,%2,%3}, {%4,%5,%6,%7}, {%8,%9}, {%0,%1,%2,%3};"
        : "+f"(d[0]), "+f"(d[1]), "+f"(d[2]), "+f"(d[3])
        : "r"(a[0]), "r"(a[1]), "r"(a[2]), "r"(a[3]), "r"(b[0]), "r"(b[1]));
}

#define APAD 36
#define BPAD 136
#define ATILE (128 * APAD)
#define BTILE (32 * BPAD)
#define GSMEM ((2 * ATILE + 2 * BTILE) * 4)

// ---------------------------------------------------------------------------
// Segmented TF32 GEMM + fused leaky-ReLU + LayerNorm, cp.async double-buffered.
// BM=128, BK=32, 8 warps. FINAL layer fuses the FC dot product into g_part.
// ---------------------------------------------------------------------------
template <int SK, bool WRITEBF, bool FINAL>
__global__ void __launch_bounds__(256) k_gemm_ln(const float* __restrict__ xin,
                                                const float* __restrict__ Wl,
                                                const float* __restrict__ wrc,
                                                const float* __restrict__ bc,
                                                const float* __restrict__ gam,
                                                const float* __restrict__ bet,
                                                float* __restrict__ out,
                                                const float* __restrict__ Wfc) {
    extern __shared__ uint32_t smem[];
    uint32_t* sA = smem;                  // 2 x ATILE
    uint32_t* sB = smem + 2 * ATILE;      // 2 x BTILE

    int tid = threadIdx.x;
    int lane = tid & 31;
    int w = tid >> 5;
    int type = blockIdx.y;
    int r0 = blockIdx.x * 128;

    uint32_t sAu = (uint32_t)__cvta_generic_to_shared(sA);
    uint32_t sBu = (uint32_t)__cvta_generic_to_shared(sB);

    constexpr int CH = SK / 32;
    int nchunk = c_nseg[type] * CH;

    auto issue = [&](int c, int buf) {
        int seg = c / CH;
        int off = (c - seg * CH) * 32;
        int rel = c_segrel[type][seg];
        const float* Ab = (seg == 0) ? xin + (size_t)type * NN * SK
                                     : g_msgs + (size_t)rel * NN * SK;
        const float* Bb = (seg == 0) ? wrc + (size_t)type * SK * HH
                                     : Wl + (size_t)rel * SK * HH;
        uint32_t dA = sAu + (uint32_t)buf * ATILE * 4;
        uint32_t dB = sBu + (uint32_t)buf * BTILE * 4;
        #pragma unroll
        for (int l = 0; l < 4; l++) {
            int f = tid + l * 256;
            int row = f >> 3;
            int c0 = (f & 7) * 4;
            int grow = r0 + row;
            if (grow > NN - 1) grow = NN - 1;   // clamp: junk rows masked at epilogue
            cp16(dA + (uint32_t)(row * APAD + c0) * 4,
                 Ab + (size_t)grow * SK + off + c0);
        }
        #pragma unroll
        for (int l = 0; l < 4; l++) {
            int f = tid + l * 256;
            int krow = f >> 5;
            int n0 = (f & 31) * 4;
            cp16(dB + (uint32_t)(krow * BPAD + n0) * 4,
                 Bb + (size_t)(off + krow) * HH + n0);
        }
        asm volatile("cp.async.commit_group;");
    };

    float acc[16][4];
    #pragma unroll
    for (int nt = 0; nt < 16; nt++)
        #pragma unroll
        for (int j = 0; j < 4; j++) acc[nt][j] = 0.f;

    issue(0, 0);
    for (int c = 0; c < nchunk; c++) {
        int buf = c & 1;
        if (c + 1 < nchunk) {
            issue(c + 1, buf ^ 1);
            asm volatile("cp.async.wait_group 1;");
        } else {
            asm volatile("cp.async.wait_group 0;");
        }
        __syncthreads();
        const uint32_t* cA = sA + buf * ATILE;
        const uint32_t* cB = sB + buf * BTILE;
        #pragma unroll
        for (int kt = 0; kt < 4; kt++) {
            int abase = (w * 16 + (lane >> 2)) * APAD + kt * 8 + (lane & 3);
            uint32_t af[4];
            af[0] = f2tf32(__uint_as_float(cA[abase]));
            af[1] = f2tf32(__uint_as_float(cA[abase + 8 * APAD]));
            af[2] = f2tf32(__uint_as_float(cA[abase + 4]));
            af[3] = f2tf32(__uint_as_float(cA[abase + 8 * APAD + 4]));
            int bb = (kt * 8 + (lane & 3)) * BPAD + (lane >> 2);
            #pragma unroll
            for (int nt = 0; nt < 16; nt++) {
                uint32_t bf[2];
                bf[0] = cB[bb + nt * 8];
                bf[1] = cB[bb + nt * 8 + 4 * BPAD];
                mma_tf32(acc[nt], af, bf);
            }
        }
        __syncthreads();
    }

    // ---- fused epilogue ----
    float inv = c_invcnt[type];
    #pragma unroll
    for (int h = 0; h < 2; h++) {
        int row = r0 + w * 16 + (lane >> 2) + h * 8;
        float v[16][2];
        float s = 0.f;
        #pragma unroll
        for (int nt = 0; nt < 16; nt++) {
            int col = nt * 8 + (lane & 3) * 2;
            float x0 = (acc[nt][2 * h] + bc[type * HH + col]) * inv;
            float x1 = (acc[nt][2 * h + 1] + bc[type * HH + col + 1]) * inv;
            x0 = (x0 >= 0.f) ? x0 : 0.01f * x0;
            x1 = (x1 >= 0.f) ? x1 : 0.01f * x1;
            v[nt][0] = x0; v[nt][1] = x1;
            s += x0 + x1;
        }
        s += __shfl_xor_sync(0xffffffffu, s, 1);
        s += __shfl_xor_sync(0xffffffffu, s, 2);
        float mu = s * (1.f / HH);
        float q = 0.f;
        #pragma unroll
        for (int nt = 0; nt < 16; nt++) {
            float d0 = v[nt][0] - mu, d1 = v[nt][1] - mu;
            v[nt][0] = d0; v[nt][1] = d1;
            q += d0 * d0 + d1 * d1;
        }
        q += __shfl_xor_sync(0xffffffffu, q, 1);
        q += __shfl_xor_sync(0xffffffffu, q, 2);
        float rs = rsqrtf(q * (1.f / HH) + 1e-5f);
        if (FINAL) {
            float dot = 0.f;
            #pragma unroll
            for (int nt = 0; nt < 16; nt++) {
                int col = nt * 8 + (lane & 3) * 2;
                float o0 = v[nt][0] * rs * gam[col] + bet[col];
                float o1 = v[nt][1] * rs * gam[col + 1] + bet[col + 1];
                dot += o0 * Wfc[type * HH + col] + o1 * Wfc[type * HH + col + 1];
            }
            dot += __shfl_xor_sync(0xffffffffu, dot, 1);
            dot += __shfl_xor_sync(0xffffffffu, dot, 2);
            if ((lane & 3) == 0 && row < NN)
                g_part[type * NN + row] = dot;
        } else if (row < NN) {
            float* op = out + (size_t)type * NN * HH + (size_t)row * HH;
            __nv_bfloat16* obf = g_xbf + (size_t)type * NN * HH + (size_t)row * HH;
            #pragma unroll
            for (int nt = 0; nt < 16; nt++) {
                int col = nt * 8 + (lane & 3) * 2;
                float2 o;
                o.x = v[nt][0] * rs * gam[col] + bet[col];
                o.y = v[nt][1] * rs * gam[col + 1] + bet[col + 1];
                *reinterpret_cast<float2*>(op + col) = o;
                if (WRITEBF)
                    *reinterpret_cast<__nv_bfloat162*>(obf + col) =
                        __floats2bfloat162_rn(o.x, o.y);
            }
        }
    }
}

// ---------------------------------------------------------------------------
// Final reduce: out[n] = sigmoid(sum_type g_part + bfc)
// ---------------------------------------------------------------------------
__global__ void k_final2(const float* __restrict__ bfc, float* __restrict__ out) {
    int n = blockIdx.x * blockDim.x + threadIdx.x;
    if (n >= NN) return;
    float s = bfc[0];
    #pragma unroll
    for (int t = 0; t < NT; t++)
        s += g_part[t * NN + n];
    out[n] = 1.f / (1.f + expf(-s));
}

// ---------------------------------------------------------------------------
// Host driver (single stream, serial)
// ---------------------------------------------------------------------------
extern "C" void kernel_launch(void* const* d_in, const int* in_sizes, int n_in,
                              void* d_out, int out_size) {
    const float* x    = (const float*)d_in[0];
    const int* edges  = (const int*)d_in[1];
    const float* Wl1  = (const float*)d_in[2];
    const float* Wr1  = (const float*)d_in[3];
    const float* b1   = (const float*)d_in[4];
    const float* Wl2  = (const float*)d_in[5];
    const float* Wr2  = (const float*)d_in[6];
    const float* b2   = (const float*)d_in[7];
    const float* Wl3  = (const float*)d_in[8];
    const float* Wr3  = (const float*)d_in[9];
    const float* b3   = (const float*)d_in[10];
    const float* g1   = (const float*)d_in[11];
    const float* be1  = (const float*)d_in[12];
    const float* g2   = (const float*)d_in[13];
    const float* be2  = (const float*)d_in[14];
    const float* g3   = (const float*)d_in[15];
    const float* be3  = (const float*)d_in[16];
    const float* Wfc  = (const float*)d_in[17];
    const float* bfc  = (const float*)d_in[18];
    float* out = (float*)d_out;

    float *p_xs0, *p_xs1, *p_wrc, *p_bc;
    int* p_cnt;
    cudaGetSymbolAddress((void**)&p_xs0, g_xs0);
    cudaGetSymbolAddress((void**)&p_xs1, g_xs1);
    cudaGetSymbolAddress((void**)&p_wrc, g_wrc);
    cudaGetSymbolAddress((void**)&p_bc, g_bc);
    cudaGetSymbolAddress((void**)&p_cnt, g_cnt);

    cudaFuncSetAttribute(k_gemm_ln<DIN, true, false>,
                         cudaFuncAttributeMaxDynamicSharedMemorySize, GSMEM);
    cudaFuncSetAttribute(k_gemm_ln<HH, true, false>,
                         cudaFuncAttributeMaxDynamicSharedMemorySize, GSMEM);
    cudaFuncSetAttribute(k_gemm_ln<HH, false, true>,
                         cudaFuncAttributeMaxDynamicSharedMemorySize, GSMEM);

    size_t wstride = (size_t)NT * HH * HH;

    // CSR build chain (g_cnt zeroed via async memset — graph-capturable)
    cudaMemsetAsync(p_cnt, 0, (size_t)NREL * NN * sizeof(int));
    k_hist_cvt<<<(NT * NN * DIN / 4 + 255) / 256, 256>>>(edges, x);
    k_scan<<<NREL, 1024>>>();
    k_fill<<<(NREL * NE / 4 + 255) / 256, 256>>>(edges);

    // layer-1 aggregation (ncu-visible launch)
    k_agg<DIN><<<dim3(NN / 8, NREL), 256>>>();

    // weight prep (all layers, single launch)
    k_comb_all<<<(WTOT + BTOT + 255) / 256, 256>>>(Wr1, Wr2, Wr3, b1, b2, b3,
                                                   p_wrc, p_bc);

    dim3 gg((NN + 127) / 128, NT);
    dim3 ga(NN / 8, NREL);

    // layer 1
    k_gemm_ln<DIN, true, false><<<gg, 256, GSMEM>>>(x, Wl1, p_wrc, p_bc,
                                                    g1, be1, p_xs0, nullptr);
    // layer 2
    k_agg<HH><<<ga, 256>>>();
    k_gemm_ln<HH, true, false><<<gg, 256, GSMEM>>>(p_xs0, Wl2, p_wrc + L1W,
                                                   p_bc + NT * HH, g2, be2,
                                                   p_xs1, nullptr);
    // layer 3 (fused FC dot -> g_part; no activation write)
    k_agg<HH><<<ga, 256>>>();
    k_gemm_ln<HH, false, true><<<gg, 256, GSMEM>>>(p_xs1, Wl3, p_wrc + L1W + LHW,
                                                   p_bc + 2 * NT * HH, g3, be3,
                                                   nullptr, Wfc);

    k_final2<<<(NN + 255) / 256, 256>>>(bfc, out);
}